// round 8
// baseline (speedup 1.0000x reference)
#include <cuda_runtime.h>
#include <cstdint>

#define N_TOKENS 8192
#define IN_CH    4096
#define OUT_CH   4096
#define RANK     16
#define TOK_BLK  16                   // tokens per k1 block
#define KC       256                  // k-chunk floats per stage (1 KB/token)
#define NCHUNK   (IN_CH / KC)         // 16
#define STAGES   3

typedef unsigned long long u64;

__device__ float g_t[N_TOKENS * RANK];   // t = x @ R^T

__device__ __forceinline__ u64 f2fma(u64 a, u64 b, u64 c) {
    u64 d;
    asm("fma.rn.f32x2 %0, %1, %2, %3;" : "=l"(d) : "l"(a), "l"(b), "l"(c));
    return d;
}
__device__ __forceinline__ u64 splat2(float v) {
    u64 d;
    asm("mov.b64 %0, {%1, %1};" : "=l"(d) : "f"(v));
    return d;
}
__device__ __forceinline__ uint32_t smem_u32(const void* p) {
    return (uint32_t)__cvta_generic_to_shared(p);
}
__device__ __forceinline__ void mbar_init(uint32_t mbar, uint32_t count) {
    asm volatile("mbarrier.init.shared.b64 [%0], %1;" :: "r"(mbar), "r"(count) : "memory");
}
__device__ __forceinline__ void mbar_expect_tx(uint32_t mbar, uint32_t bytes) {
    asm volatile("mbarrier.arrive.expect_tx.shared.b64 _, [%0], %1;"
                 :: "r"(mbar), "r"(bytes) : "memory");
}
__device__ __forceinline__ void bulk_g2s(uint32_t sdst, const void* gsrc,
                                         uint32_t bytes, uint32_t mbar) {
    asm volatile(
        "cp.async.bulk.shared::cta.global.mbarrier::complete_tx::bytes "
        "[%0], [%1], %2, [%3];"
        :: "r"(sdst), "l"(gsrc), "r"(bytes), "r"(mbar) : "memory");
}
__device__ __forceinline__ void mbar_wait(uint32_t mbar, uint32_t phase) {
    asm volatile(
        "{\n\t"
        ".reg .pred P;\n\t"
        "WL_%=:\n\t"
        "mbarrier.try_wait.parity.acquire.cta.shared::cta.b64 P, [%0], %1;\n\t"
        "@P bra WD_%=;\n\t"
        "bra WL_%=;\n\t"
        "WD_%=:\n\t"
        "}"
        :: "r"(mbar), "r"(phase) : "memory");
}

// ----------------------------------------------------------------------------
// Kernel 1: t[n, r] = sum_k x[n,k] * R[r,k]
// x streamed HBM->SMEM via cp.async.bulk (1 KB contiguous bursts per token
// row) through a 3-stage mbarrier pipeline — bypasses the per-lane LDG queue
// that capped all prior k1 variants at ~1.9 TB/s.
// 256 thr = 8 warps = 4 token-groups x 2 rank-halves; warp = 4 tok x 8 ranks
// (acc 32 u64). x from conflict-free LDS.128; R via L1-hot LDG.
// ----------------------------------------------------------------------------
__global__ void __launch_bounds__(256)
k1_xRt(const float* __restrict__ x, const float* __restrict__ Rm) {
    __shared__ __align__(16) float xs[STAGES][TOK_BLK][KC];   // 48 KB
    __shared__ __align__(8)  u64   mbar[STAGES];

    const int tid   = threadIdx.x;
    const int warp  = tid >> 5;
    const int lane  = tid & 31;
    const int tg    = warp >> 1;             // token group 0..3
    const int rbase = (warp & 1) * 8;        // rank half
    const int tok0  = blockIdx.x * TOK_BLK + tg * 4;

    const float* xg = x + (size_t)blockIdx.x * TOK_BLK * IN_CH;
    const float* Rp = Rm + (size_t)rbase * IN_CH + lane * 4;

    if (tid == 0) {
#pragma unroll
        for (int s = 0; s < STAGES; s++) mbar_init(smem_u32(&mbar[s]), 1);
    }
    __syncthreads();

    // prologue: issue chunks 0, 1
    if (tid == 0) {
#pragma unroll
        for (int c = 0; c < STAGES - 1; c++) {
            const uint32_t mb = smem_u32(&mbar[c]);
            mbar_expect_tx(mb, TOK_BLK * KC * 4);
#pragma unroll
            for (int t = 0; t < TOK_BLK; t++)
                bulk_g2s(smem_u32(&xs[c][t][0]),
                         xg + (size_t)t * IN_CH + c * KC, KC * 4, mb);
        }
    }

    u64 acc[4][8];
#pragma unroll
    for (int t = 0; t < 4; t++)
#pragma unroll
        for (int r = 0; r < 8; r++) acc[t][r] = 0ull;

#pragma unroll 1
    for (int c = 0; c < NCHUNK; c++) {
        // issue chunk c+2 into buffer (c+2)%3 (freed by sync at end of c-1)
        if (tid == 0 && c + STAGES - 1 < NCHUNK) {
            const int pc = c + STAGES - 1;
            const int pb = pc % STAGES;
            const uint32_t mb = smem_u32(&mbar[pb]);
            mbar_expect_tx(mb, TOK_BLK * KC * 4);
#pragma unroll
            for (int t = 0; t < TOK_BLK; t++)
                bulk_g2s(smem_u32(&xs[pb][t][0]),
                         xg + (size_t)t * IN_CH + pc * KC, KC * 4, mb);
        }

        const int buf = c % STAGES;
        mbar_wait(smem_u32(&mbar[buf]), (uint32_t)((c / STAGES) & 1));

        // compute chunk c: 2 sub-iters of 128 floats
#pragma unroll
        for (int sub = 0; sub < KC / 128; sub++) {
            const int ks = sub * 128 + lane * 4;
            const int kf = c * KC + sub * 128;
            const ulonglong2 x0 = *reinterpret_cast<const ulonglong2*>(&xs[buf][tg * 4 + 0][ks]);
            const ulonglong2 x1 = *reinterpret_cast<const ulonglong2*>(&xs[buf][tg * 4 + 1][ks]);
            const ulonglong2 x2 = *reinterpret_cast<const ulonglong2*>(&xs[buf][tg * 4 + 2][ks]);
            const ulonglong2 x3 = *reinterpret_cast<const ulonglong2*>(&xs[buf][tg * 4 + 3][ks]);
#pragma unroll
            for (int r = 0; r < 8; r++) {
                const ulonglong2 rv =
                    *reinterpret_cast<const ulonglong2*>(Rp + (size_t)r * IN_CH + kf);
                acc[0][r] = f2fma(x0.x, rv.x, acc[0][r]);
                acc[0][r] = f2fma(x0.y, rv.y, acc[0][r]);
                acc[1][r] = f2fma(x1.x, rv.x, acc[1][r]);
                acc[1][r] = f2fma(x1.y, rv.y, acc[1][r]);
                acc[2][r] = f2fma(x2.x, rv.x, acc[2][r]);
                acc[2][r] = f2fma(x2.y, rv.y, acc[2][r]);
                acc[3][r] = f2fma(x3.x, rv.x, acc[3][r]);
                acc[3][r] = f2fma(x3.y, rv.y, acc[3][r]);
            }
        }
        __syncthreads();   // all warps done with buffer `buf` -> reusable
    }

    // cross-lane reduce; lane 0 writes the warp's 8-rank half of each t row
#pragma unroll
    for (int t = 0; t < 4; t++) {
        float s[8];
#pragma unroll
        for (int r = 0; r < 8; r++) {
            float2 v = *reinterpret_cast<float2*>(&acc[t][r]);
            s[r] = v.x + v.y;
        }
#pragma unroll
        for (int off = 16; off > 0; off >>= 1) {
#pragma unroll
            for (int r = 0; r < 8; r++)
                s[r] += __shfl_xor_sync(0xffffffffu, s[r], off);
        }
        if (lane == 0) {
            float4* o = reinterpret_cast<float4*>(
                g_t + (size_t)(tok0 + t) * RANK + rbase);
            o[0] = make_float4(s[0], s[1], s[2], s[3]);
            o[1] = make_float4(s[4], s[5], s[6], s[7]);
        }
    }
}

// ----------------------------------------------------------------------------
// Kernel 2 (exact round-1 code — best measured at 37 us):
// out[n, o] = bias[o] + sum_r t[n,r] * L[o,r]
// Tile: 32 tokens x 512 outputs per block (128 threads, 4 consecutive o each).
// L chunk transposed into smem (LDS.128), t pre-splatted as f32x2 pairs,
// L register value reused across 8-token blocks.
// ----------------------------------------------------------------------------
__global__ void __launch_bounds__(128)
k2_tLt(const float* __restrict__ Lm, const float* __restrict__ bias,
       float* __restrict__ out) {
    __shared__ __align__(16) float Lt[16][512];     // Lt[r][o_local]
    __shared__ __align__(16) u64   ts2[32][16];     // splatted t[tok][r]

    const int tid = threadIdx.x;
    const int bt = blockIdx.x >> 3;     // token tile 0..255
    const int bo = blockIdx.x & 7;      // o chunk 0..7
    const int obase   = bo * 512;
    const int tokbase = bt * 32;

    // stage L chunk transposed: 512 rows of 16 floats
#pragma unroll
    for (int j = 0; j < 4; j++) {
        const int ol = tid + 128 * j;
        const float4* lr = reinterpret_cast<const float4*>(Lm + (size_t)(obase + ol) * RANK);
        float4 a = lr[0], b = lr[1], c = lr[2], d = lr[3];
        Lt[0][ol]  = a.x; Lt[1][ol]  = a.y; Lt[2][ol]  = a.z; Lt[3][ol]  = a.w;
        Lt[4][ol]  = b.x; Lt[5][ol]  = b.y; Lt[6][ol]  = b.z; Lt[7][ol]  = b.w;
        Lt[8][ol]  = c.x; Lt[9][ol]  = c.y; Lt[10][ol] = c.z; Lt[11][ol] = c.w;
        Lt[12][ol] = d.x; Lt[13][ol] = d.y; Lt[14][ol] = d.z; Lt[15][ol] = d.w;
    }

    // stage t rows, pre-splatted to f32x2 (both halves = t value)
    {
        const float4* tp = reinterpret_cast<const float4*>(g_t + (size_t)tokbase * RANK);
        float4 v = tp[tid];                 // 128 threads * 4 = 512 floats = 32x16
        const int tok = tid >> 2;
        const int r0  = (tid & 3) * 4;
        ts2[tok][r0 + 0] = splat2(v.x);
        ts2[tok][r0 + 1] = splat2(v.y);
        ts2[tok][r0 + 2] = splat2(v.z);
        ts2[tok][r0 + 3] = splat2(v.w);
    }

    const ulonglong2 bv = *reinterpret_cast<const ulonglong2*>(bias + obase + tid * 4);
    __syncthreads();

    const int o4 = tid * 4;
#pragma unroll 1
    for (int tb = 0; tb < 4; tb++) {
        u64 accA[8], accB[8];
#pragma unroll
        for (int tk = 0; tk < 8; tk++) { accA[tk] = bv.x; accB[tk] = bv.y; }

#pragma unroll
        for (int r = 0; r < 16; r++) {
            ulonglong2 Lv = *reinterpret_cast<const ulonglong2*>(&Lt[r][o4]);
#pragma unroll
            for (int tk = 0; tk < 8; tk++) {
                u64 t2 = ts2[tb * 8 + tk][r];
                accA[tk] = f2fma(t2, Lv.x, accA[tk]);
                accB[tk] = f2fma(t2, Lv.y, accB[tk]);
            }
        }

#pragma unroll
        for (int tk = 0; tk < 8; tk++) {
            ulonglong2 o;
            o.x = accA[tk];
            o.y = accB[tk];
            *reinterpret_cast<ulonglong2*>(
                out + (size_t)(tokbase + tb * 8 + tk) * OUT_CH + obase + o4) = o;
        }
    }
}

extern "C" void kernel_launch(void* const* d_in, const int* in_sizes, int n_in,
                              void* d_out, int out_size) {
    (void)in_sizes; (void)n_in; (void)out_size;
    const float* x    = (const float*)d_in[0];   // [8192, 4096]
    const float* Lm   = (const float*)d_in[1];   // [4096, 16]
    const float* Rm   = (const float*)d_in[2];   // [16, 4096]
    const float* bias = (const float*)d_in[3];   // [4096]
    float* out = (float*)d_out;                  // [8192, 4096]

    k1_xRt<<<N_TOKENS / TOK_BLK, 256>>>(x, Rm);
    k2_tLt<<<(N_TOKENS / 32) * (OUT_CH / 512), 128>>>(Lm, bias, out);
}

// round 9
// speedup vs baseline: 1.0737x; 1.0737x over previous
#include <cuda_runtime.h>
#include <cstdint>

#define N_TOKENS 8192
#define IN_CH    4096
#define OUT_CH   4096
#define RANK     16
#define KSLICES  8
#define KS       (IN_CH / KSLICES)    // 512 k per slice

typedef unsigned long long u64;

// partial t sums: g_tp[slice][token][rank]
__device__ float g_tp[KSLICES][N_TOKENS][RANK];

__device__ __forceinline__ u64 f2fma(u64 a, u64 b, u64 c) {
    u64 d;
    asm("fma.rn.f32x2 %0, %1, %2, %3;" : "=l"(d) : "l"(a), "l"(b), "l"(c));
    return d;
}
__device__ __forceinline__ u64 splat2(float v) {
    u64 d;
    asm("mov.b64 %0, {%1, %1};" : "=l"(d) : "f"(v));
    return d;
}

// ----------------------------------------------------------------------------
// Kernel 1 (k-sliced): g_tp[ks][n][r] = sum_{k in slice ks} x[n,k] * R[r,k]
// grid = 256 token-tiles x 8 k-slices. Block: 512 thr = 16 warps
//   warp = (token-quad 0..7) x (rank-half 0..1): 4 tok x 8 ranks, acc 32 u64.
// R slice (16 x 512 f32 = 32 KB) staged in smem once, ONE barrier.
// x read exactly once chip-wide. Short k-chains (4 iters of 128).
// ----------------------------------------------------------------------------
__global__ void __launch_bounds__(512)
k1_xRt(const float* __restrict__ x, const float* __restrict__ Rm) {
    __shared__ __align__(16) float Rs[RANK][KS];   // 32 KB

    const int tid   = threadIdx.x;
    const int warp  = tid >> 5;
    const int lane  = tid & 31;
    const int ks    = blockIdx.x & (KSLICES - 1);
    const int tile  = blockIdx.x >> 3;
    const int k0    = ks * KS;
    const int tokq  = warp >> 1;               // 0..7
    const int rbase = (warp & 1) * 8;          // 0 or 8
    const int tok0  = tile * 32 + tokq * 4;

    // stage R slice: 2048 float4, 4 per thread, coalesced
#pragma unroll
    for (int j = 0; j < 4; j++) {
        const int linear = tid + 512 * j;          // float4 index
        const int row    = linear >> 7;            // 128 float4 per row
        const int colf   = (linear & 127) << 2;
        *reinterpret_cast<float4*>(&Rs[row][colf]) =
            *reinterpret_cast<const float4*>(&Rm[(size_t)row * IN_CH + k0 + colf]);
    }
    __syncthreads();

    u64 acc[4][8];
#pragma unroll
    for (int t = 0; t < 4; t++)
#pragma unroll
        for (int r = 0; r < 8; r++) acc[t][r] = 0ull;

    const float* xr = x + (size_t)tok0 * IN_CH + k0 + lane * 4;

#pragma unroll
    for (int i = 0; i < KS / 128; i++) {           // 4 iters
        const int kk = i * 128;
        const uint4 xv0 = *reinterpret_cast<const uint4*>(xr + 0 * IN_CH + kk);
        const uint4 xv1 = *reinterpret_cast<const uint4*>(xr + 1 * IN_CH + kk);
        const uint4 xv2 = *reinterpret_cast<const uint4*>(xr + 2 * IN_CH + kk);
        const uint4 xv3 = *reinterpret_cast<const uint4*>(xr + 3 * IN_CH + kk);
        const ulonglong2 x0 = *reinterpret_cast<const ulonglong2*>(&xv0);
        const ulonglong2 x1 = *reinterpret_cast<const ulonglong2*>(&xv1);
        const ulonglong2 x2 = *reinterpret_cast<const ulonglong2*>(&xv2);
        const ulonglong2 x3 = *reinterpret_cast<const ulonglong2*>(&xv3);
        const int kl = kk + lane * 4;
#pragma unroll
        for (int r = 0; r < 8; r++) {
            const ulonglong2 rv = *reinterpret_cast<const ulonglong2*>(&Rs[rbase + r][kl]);
            acc[0][r] = f2fma(x0.x, rv.x, acc[0][r]);
            acc[0][r] = f2fma(x0.y, rv.y, acc[0][r]);
            acc[1][r] = f2fma(x1.x, rv.x, acc[1][r]);
            acc[1][r] = f2fma(x1.y, rv.y, acc[1][r]);
            acc[2][r] = f2fma(x2.x, rv.x, acc[2][r]);
            acc[2][r] = f2fma(x2.y, rv.y, acc[2][r]);
            acc[3][r] = f2fma(x3.x, rv.x, acc[3][r]);
            acc[3][r] = f2fma(x3.y, rv.y, acc[3][r]);
        }
    }

    // cross-lane reduce; lane 0 writes this warp's 8-rank partial
#pragma unroll
    for (int t = 0; t < 4; t++) {
        float s[8];
#pragma unroll
        for (int r = 0; r < 8; r++) {
            float2 v = *reinterpret_cast<float2*>(&acc[t][r]);
            s[r] = v.x + v.y;
        }
#pragma unroll
        for (int off = 16; off > 0; off >>= 1) {
#pragma unroll
            for (int r = 0; r < 8; r++)
                s[r] += __shfl_xor_sync(0xffffffffu, s[r], off);
        }
        if (lane == 0) {
            float4* o = reinterpret_cast<float4*>(&g_tp[ks][tok0 + t][rbase]);
            o[0] = make_float4(s[0], s[1], s[2], s[3]);
            o[1] = make_float4(s[4], s[5], s[6], s[7]);
        }
    }
}

// ----------------------------------------------------------------------------
// Kernel 2 (round-1 structure, 37 us proven) + 8-partial t sum at staging.
// out[n, o] = bias[o] + sum_r t[n,r] * L[o,r]
// ----------------------------------------------------------------------------
__global__ void __launch_bounds__(128)
k2_tLt(const float* __restrict__ Lm, const float* __restrict__ bias,
       float* __restrict__ out) {
    __shared__ __align__(16) float Lt[16][512];     // Lt[r][o_local]
    __shared__ __align__(16) u64   ts2[32][16];     // splatted t[tok][r]

    const int tid = threadIdx.x;
    const int bt = blockIdx.x >> 3;     // token tile 0..255
    const int bo = blockIdx.x & 7;      // o chunk 0..7
    const int obase   = bo * 512;
    const int tokbase = bt * 32;

    // stage L chunk transposed: 512 rows of 16 floats
#pragma unroll
    for (int j = 0; j < 4; j++) {
        const int ol = tid + 128 * j;
        const float4* lr = reinterpret_cast<const float4*>(Lm + (size_t)(obase + ol) * RANK);
        float4 a = lr[0], b = lr[1], c = lr[2], d = lr[3];
        Lt[0][ol]  = a.x; Lt[1][ol]  = a.y; Lt[2][ol]  = a.z; Lt[3][ol]  = a.w;
        Lt[4][ol]  = b.x; Lt[5][ol]  = b.y; Lt[6][ol]  = b.z; Lt[7][ol]  = b.w;
        Lt[8][ol]  = c.x; Lt[9][ol]  = c.y; Lt[10][ol] = c.z; Lt[11][ol] = c.w;
        Lt[12][ol] = d.x; Lt[13][ol] = d.y; Lt[14][ol] = d.z; Lt[15][ol] = d.w;
    }

    // stage t rows: sum the 8 k-slice partials, then splat to f32x2
    {
        const int fidx = tid;                 // float4 index within 32x16 tile
        float4 v = make_float4(0.f, 0.f, 0.f, 0.f);
#pragma unroll
        for (int s = 0; s < KSLICES; s++) {
            const float4 p = *(reinterpret_cast<const float4*>(
                &g_tp[s][tokbase][0]) + fidx);
            v.x += p.x; v.y += p.y; v.z += p.z; v.w += p.w;
        }
        const int tok = tid >> 2;
        const int r0  = (tid & 3) * 4;
        ts2[tok][r0 + 0] = splat2(v.x);
        ts2[tok][r0 + 1] = splat2(v.y);
        ts2[tok][r0 + 2] = splat2(v.z);
        ts2[tok][r0 + 3] = splat2(v.w);
    }

    const ulonglong2 bv = *reinterpret_cast<const ulonglong2*>(bias + obase + tid * 4);
    __syncthreads();

    const int o4 = tid * 4;
#pragma unroll 1
    for (int tb = 0; tb < 4; tb++) {
        u64 accA[8], accB[8];
#pragma unroll
        for (int tk = 0; tk < 8; tk++) { accA[tk] = bv.x; accB[tk] = bv.y; }

#pragma unroll
        for (int r = 0; r < 16; r++) {
            ulonglong2 Lv = *reinterpret_cast<const ulonglong2*>(&Lt[r][o4]);
#pragma unroll
            for (int tk = 0; tk < 8; tk++) {
                u64 t2 = ts2[tb * 8 + tk][r];
                accA[tk] = f2fma(t2, Lv.x, accA[tk]);
                accB[tk] = f2fma(t2, Lv.y, accB[tk]);
            }
        }

#pragma unroll
        for (int tk = 0; tk < 8; tk++) {
            ulonglong2 o;
            o.x = accA[tk];
            o.y = accB[tk];
            *reinterpret_cast<ulonglong2*>(
                out + (size_t)(tokbase + tb * 8 + tk) * OUT_CH + obase + o4) = o;
        }
    }
}

// empty kernels to shift ncu's -s 5 -c 1 capture onto k1 (launch #6)
__global__ void k_nop() {}

extern "C" void kernel_launch(void* const* d_in, const int* in_sizes, int n_in,
                              void* d_out, int out_size) {
    (void)in_sizes; (void)n_in; (void)out_size;
    const float* x    = (const float*)d_in[0];   // [8192, 4096]
    const float* Lm   = (const float*)d_in[1];   // [4096, 16]
    const float* Rm   = (const float*)d_in[2];   // [16, 4096]
    const float* bias = (const float*)d_in[3];   // [4096]
    float* out = (float*)d_out;                  // [8192, 4096]

    k1_xRt<<<(N_TOKENS / 32) * KSLICES, 512>>>(x, Rm);
    k2_tLt<<<(N_TOKENS / 32) * (OUT_CH / 512), 128>>>(Lm, bias, out);
    // parity dummies: 5 launches/iter -> ncu (-s 5) captures k1 next iter
    k_nop<<<1, 1>>>();
    k_nop<<<1, 1>>>();
    k_nop<<<1, 1>>>();
}

// round 10
// speedup vs baseline: 1.2353x; 1.1505x over previous
#include <cuda_runtime.h>
#include <cstdint>

#define N_TOKENS 8192
#define IN_CH    4096
#define OUT_CH   4096
#define RANK     16
#define KSLICES  2
#define KS       (IN_CH / KSLICES)    // 2048 k per slice
#define K1_SMEM  (RANK * KS * 4)      // 128 KB
#define OC       1024                 // k2 o-chunk
#define K2_SMEM  (16 * OC * 4 + 32 * 16 * 8)   // Lt 64 KB + ts2 4 KB

typedef unsigned long long u64;

// partial t sums per k-slice: g_tp[slice][token][rank]
__device__ float g_tp[KSLICES][N_TOKENS][RANK];

__device__ __forceinline__ u64 f2fma(u64 a, u64 b, u64 c) {
    u64 d;
    asm("fma.rn.f32x2 %0, %1, %2, %3;" : "=l"(d) : "l"(a), "l"(b), "l"(c));
    return d;
}
__device__ __forceinline__ u64 splat2(float v) {
    u64 d;
    asm("mov.b64 %0, {%1, %1};" : "=l"(d) : "f"(v));
    return d;
}

// ----------------------------------------------------------------------------
// Kernel 1: g_tp[ks][n][r] = sum_{k in slice} x[n,k] * R[r,k]
// KSLICES=2: R-slice (16 x 2048 = 128 KB) staged ONCE per block in dynamic
// smem -> R L2 traffic 64 MB total (was ~0.5 GB). x amplification only 2x,
// and slice-pair blocks are ADJACENT bids -> co-scheduled -> x L2 reuse.
// 512 thr = 16 warps = 8 token-quads x 2 rank-halves; warp: 4 tok x 8 ranks.
// ----------------------------------------------------------------------------
__global__ void __launch_bounds__(512)
k1_xRt(const float* __restrict__ x, const float* __restrict__ Rm) {
    extern __shared__ __align__(16) float Rs[];   // [RANK][KS] = 128 KB

    const int tid   = threadIdx.x;
    const int warp  = tid >> 5;
    const int lane  = tid & 31;
    const int ks    = blockIdx.x & (KSLICES - 1); // adjacent bids share tile
    const int tile  = blockIdx.x >> 1;
    const int k0    = ks * KS;
    const int tokq  = warp >> 1;                  // 0..7
    const int rbase = (warp & 1) * 8;
    const int tok0  = tile * 32 + tokq * 4;

    // stage R slice: 8192 float4, 16 per thread, coalesced
#pragma unroll
    for (int j = 0; j < 16; j++) {
        const int linear = tid + 512 * j;         // float4 index
        const int row    = linear >> 9;           // KS/4 = 512 float4 per row
        const int colf   = (linear & 511) << 2;
        *reinterpret_cast<float4*>(&Rs[row * KS + colf]) =
            *reinterpret_cast<const float4*>(&Rm[(size_t)row * IN_CH + k0 + colf]);
    }
    __syncthreads();

    u64 acc[4][8];
#pragma unroll
    for (int t = 0; t < 4; t++)
#pragma unroll
        for (int r = 0; r < 8; r++) acc[t][r] = 0ull;

    const float* xr = x + (size_t)tok0 * IN_CH + k0 + lane * 4;
    const float* Rw = Rs + (size_t)rbase * KS + lane * 4;

#pragma unroll 4
    for (int i = 0; i < KS / 128; i++) {          // 16 iters
        const int kk = i * 128;
        const uint4 xv0 = *reinterpret_cast<const uint4*>(xr + 0 * IN_CH + kk);
        const uint4 xv1 = *reinterpret_cast<const uint4*>(xr + 1 * IN_CH + kk);
        const uint4 xv2 = *reinterpret_cast<const uint4*>(xr + 2 * IN_CH + kk);
        const uint4 xv3 = *reinterpret_cast<const uint4*>(xr + 3 * IN_CH + kk);
        const ulonglong2 x0 = *reinterpret_cast<const ulonglong2*>(&xv0);
        const ulonglong2 x1 = *reinterpret_cast<const ulonglong2*>(&xv1);
        const ulonglong2 x2 = *reinterpret_cast<const ulonglong2*>(&xv2);
        const ulonglong2 x3 = *reinterpret_cast<const ulonglong2*>(&xv3);
#pragma unroll
        for (int r = 0; r < 8; r++) {
            const ulonglong2 rv =
                *reinterpret_cast<const ulonglong2*>(Rw + (size_t)r * KS + kk);
            acc[0][r] = f2fma(x0.x, rv.x, acc[0][r]);
            acc[0][r] = f2fma(x0.y, rv.y, acc[0][r]);
            acc[1][r] = f2fma(x1.x, rv.x, acc[1][r]);
            acc[1][r] = f2fma(x1.y, rv.y, acc[1][r]);
            acc[2][r] = f2fma(x2.x, rv.x, acc[2][r]);
            acc[2][r] = f2fma(x2.y, rv.y, acc[2][r]);
            acc[3][r] = f2fma(x3.x, rv.x, acc[3][r]);
            acc[3][r] = f2fma(x3.y, rv.y, acc[3][r]);
        }
    }

    // cross-lane reduce; lane 0 writes this warp's 8-rank partial
#pragma unroll
    for (int t = 0; t < 4; t++) {
        float s[8];
#pragma unroll
        for (int r = 0; r < 8; r++) {
            float2 v = *reinterpret_cast<float2*>(&acc[t][r]);
            s[r] = v.x + v.y;
        }
#pragma unroll
        for (int off = 16; off > 0; off >>= 1) {
#pragma unroll
            for (int r = 0; r < 8; r++)
                s[r] += __shfl_xor_sync(0xffffffffu, s[r], off);
        }
        if (lane == 0) {
            float4* o = reinterpret_cast<float4*>(&g_tp[ks][tok0 + t][rbase]);
            o[0] = make_float4(s[0], s[1], s[2], s[3]);
            o[1] = make_float4(s[4], s[5], s[6], s[7]);
        }
    }
}

// ----------------------------------------------------------------------------
// Kernel 2: out[n, o] = bias[o] + sum_r t[n,r] * L[o,r]
// 128 thr x 8 outputs = 1024-o chunk (Lt 64 KB dynamic smem); 32 tokens/block.
// 8 o/thread halves the t2-broadcast-LDS per FFMA2 vs the 37us version.
// ----------------------------------------------------------------------------
__global__ void __launch_bounds__(128)
k2_tLt(const float* __restrict__ Lm, const float* __restrict__ bias,
       float* __restrict__ out) {
    extern __shared__ __align__(16) float k2smem[];
    float* Lt  = k2smem;                               // [16][OC]
    u64*   ts2 = reinterpret_cast<u64*>(k2smem + 16 * OC);   // [32][16]

    const int tid = threadIdx.x;
    const int bo  = blockIdx.x & 3;      // 4 o-chunks of 1024
    const int bt  = blockIdx.x >> 2;     // 256 token tiles
    const int obase   = bo * OC;
    const int tokbase = bt * 32;

    // stage L chunk transposed: 1024 rows of 16 floats
#pragma unroll
    for (int j = 0; j < 8; j++) {
        const int ol = tid + 128 * j;
        const float4* lr = reinterpret_cast<const float4*>(Lm + (size_t)(obase + ol) * RANK);
        float4 a = lr[0], b = lr[1], c = lr[2], d = lr[3];
        Lt[0 * OC + ol]  = a.x; Lt[1 * OC + ol]  = a.y; Lt[2 * OC + ol]  = a.z; Lt[3 * OC + ol]  = a.w;
        Lt[4 * OC + ol]  = b.x; Lt[5 * OC + ol]  = b.y; Lt[6 * OC + ol]  = b.z; Lt[7 * OC + ol]  = b.w;
        Lt[8 * OC + ol]  = c.x; Lt[9 * OC + ol]  = c.y; Lt[10 * OC + ol] = c.z; Lt[11 * OC + ol] = c.w;
        Lt[12 * OC + ol] = d.x; Lt[13 * OC + ol] = d.y; Lt[14 * OC + ol] = d.z; Lt[15 * OC + ol] = d.w;
    }

    // stage t rows: sum the 2 k-slice partials, then splat to f32x2
    {
        const float4 p0 = *(reinterpret_cast<const float4*>(&g_tp[0][tokbase][0]) + tid);
        const float4 p1 = *(reinterpret_cast<const float4*>(&g_tp[1][tokbase][0]) + tid);
        const int tok = tid >> 2;
        const int r0  = (tid & 3) * 4;
        ts2[tok * 16 + r0 + 0] = splat2(p0.x + p1.x);
        ts2[tok * 16 + r0 + 1] = splat2(p0.y + p1.y);
        ts2[tok * 16 + r0 + 2] = splat2(p0.z + p1.z);
        ts2[tok * 16 + r0 + 3] = splat2(p0.w + p1.w);
    }

    const int o8 = tid * 8;
    const ulonglong2 bv0 = *reinterpret_cast<const ulonglong2*>(bias + obase + o8);
    const ulonglong2 bv1 = *reinterpret_cast<const ulonglong2*>(bias + obase + o8 + 4);
    __syncthreads();

#pragma unroll 1
    for (int tb = 0; tb < 4; tb++) {
        u64 accA[8][2], accB[8][2];
#pragma unroll
        for (int tk = 0; tk < 8; tk++) {
            accA[tk][0] = bv0.x; accA[tk][1] = bv0.y;
            accB[tk][0] = bv1.x; accB[tk][1] = bv1.y;
        }

#pragma unroll
        for (int r = 0; r < 16; r++) {
            const ulonglong2 LvA = *reinterpret_cast<const ulonglong2*>(&Lt[r * OC + o8]);
            const ulonglong2 LvB = *reinterpret_cast<const ulonglong2*>(&Lt[r * OC + o8 + 4]);
#pragma unroll
            for (int tk = 0; tk < 8; tk++) {
                const u64 t2 = ts2[(tb * 8 + tk) * 16 + r];   // broadcast LDS.64
                accA[tk][0] = f2fma(t2, LvA.x, accA[tk][0]);
                accA[tk][1] = f2fma(t2, LvA.y, accA[tk][1]);
                accB[tk][0] = f2fma(t2, LvB.x, accB[tk][0]);
                accB[tk][1] = f2fma(t2, LvB.y, accB[tk][1]);
            }
        }

#pragma unroll
        for (int tk = 0; tk < 8; tk++) {
            float* op = out + (size_t)(tokbase + tb * 8 + tk) * OUT_CH + obase + o8;
            ulonglong2 oA, oB;
            oA.x = accA[tk][0]; oA.y = accA[tk][1];
            oB.x = accB[tk][0]; oB.y = accB[tk][1];
            *reinterpret_cast<ulonglong2*>(op)     = oA;
            *reinterpret_cast<ulonglong2*>(op + 4) = oB;
        }
    }
}

extern "C" void kernel_launch(void* const* d_in, const int* in_sizes, int n_in,
                              void* d_out, int out_size) {
    (void)in_sizes; (void)n_in; (void)out_size;
    const float* x    = (const float*)d_in[0];   // [8192, 4096]
    const float* Lm   = (const float*)d_in[1];   // [4096, 16]
    const float* Rm   = (const float*)d_in[2];   // [16, 4096]
    const float* bias = (const float*)d_in[3];   // [4096]
    float* out = (float*)d_out;                  // [8192, 4096]

    static int attr_done = 0;
    if (!attr_done) {
        cudaFuncSetAttribute(k1_xRt, cudaFuncAttributeMaxDynamicSharedMemorySize, K1_SMEM);
        cudaFuncSetAttribute(k2_tLt, cudaFuncAttributeMaxDynamicSharedMemorySize, K2_SMEM);
        attr_done = 1;
    }

    k1_xRt<<<(N_TOKENS / 32) * KSLICES, 512, K1_SMEM>>>(x, Rm);
    k2_tLt<<<(N_TOKENS / 32) * (OUT_CH / OC), 128, K2_SMEM>>>(Lm, bias, out);
}